// round 1
// baseline (speedup 1.0000x reference)
#include <cuda_runtime.h>

// SinusoidalEmbedding: out[b][s][d] = emb_table[x[b][s]][d] + PE[s][d]
// PE[s][2i]   = sin(s * f_i),  PE[s][2i+1] = cos(s * f_i),  f_i = 10000^(-2i/1024)
//
// Strategy:
//  - One CTA handles an S_TILE=8 strip of positions, full D=1024.
//  - Phase 1: build the PE tile in shared. Per frequency column: one exp2f for
//    f_i, two accurate sincosf (anchor at s_base, and the step rotation
//    (sin f, cos f)), then S_TILE angle-addition rotations (4 FMA each).
//    This keeps total sincosf count at ~262K instead of 33.5M.
//  - Phase 2: for each of the 8 positions x 8 batch rows, coalesced float4
//    gather from emb_table + shared PE add + coalesced float4 store.
//    PE reuse across the batch dimension comes for free from shared memory.

#define D_M     1024
#define HALF_D  512
#define BQ      8
#define S_LEN   4096
#define S_TILE  8
#define THREADS 256

__global__ __launch_bounds__(THREADS)
void sinemb_kernel(const void* __restrict__ xraw,
                   const float* __restrict__ emb,
                   float* __restrict__ out)
{
    __shared__ float pe[S_TILE][D_M];       // 32 KB
    __shared__ int   rows[BQ][S_TILE];
    __shared__ int   is64_s;

    const int t      = threadIdx.x;
    const int s_base = blockIdx.x * S_TILE;

    // ---- detect index dtype (int64 vs int32) ----
    // int64 little-endian with values < 50257 => every high word is 0.
    // int32 data: odd words are independent indices; P(4 zeros) ~ (2e-5)^4 ~ 0.
    if (t == 0) {
        const unsigned int* w = (const unsigned int*)xraw;
        is64_s = ((w[1] | w[3] | w[5] | w[7]) == 0u) ? 1 : 0;
    }
    __syncthreads();
    const int is64 = is64_s;

    // ---- load the 64 gather indices for this strip ----
    if (t < BQ * S_TILE) {
        int b = t / S_TILE, s = t % S_TILE;
        long long pos = (long long)b * S_LEN + (s_base + s);
        int idx;
        if (is64) idx = (int)((const long long*)xraw)[pos];
        else      idx = ((const int*)xraw)[pos];
        rows[b][s] = idx;
    }

    // ---- phase 1: PE tile via anchored rotation recurrence ----
    // f_i = 2^(c_exp * i),  c_exp = -2*log2(10000)/1024
    const float c_exp = -0.02595256324130752f;
    for (int i = t; i < HALF_D; i += THREADS) {
        float f = exp2f(c_exp * (float)i);
        float s0, c0, sf, cf;
        sincosf((float)s_base * f, &s0, &c0);   // anchor (accurate reduction)
        sincosf(f, &sf, &cf);                   // rotation step
        #pragma unroll
        for (int k = 0; k < S_TILE; k++) {
            ((float2*)pe[k])[i] = make_float2(s0, c0);
            float s1 = fmaf(s0, cf,  c0 * sf);
            float c1 = fmaf(c0, cf, -(s0 * sf));
            s0 = s1; c0 = c1;
        }
    }
    __syncthreads();

    // ---- phase 2: gather + add + store, fully coalesced float4 ----
    #pragma unroll 1
    for (int s = 0; s < S_TILE; s++) {
        float4 p = ((const float4*)pe[s])[t];   // conflict-free LDS.128
        long long sg = s_base + s;
        #pragma unroll
        for (int b = 0; b < BQ; b++) {
            long long row = rows[b][s];
            float4 e = __ldg(&((const float4*)emb)[row * (D_M / 4) + t]);
            float4 o;
            o.x = e.x + p.x; o.y = e.y + p.y;
            o.z = e.z + p.z; o.w = e.w + p.w;
            ((float4*)out)[((long long)b * S_LEN + sg) * (D_M / 4) + t] = o;
        }
    }
}

extern "C" void kernel_launch(void* const* d_in, const int* in_sizes, int n_in,
                              void* d_out, int out_size)
{
    const void*  x   = d_in[0];                 // [8, 4096] int64 (or int32)
    const float* emb = (const float*)d_in[1];   // [50257, 1024] fp32
    float*       out = (float*)d_out;           // [8, 4096, 1024] fp32

    dim3 grid(S_LEN / S_TILE);                  // 512 CTAs
    sinemb_kernel<<<grid, THREADS>>>(x, emb, out);
}

// round 2
// speedup vs baseline: 1.2362x; 1.2362x over previous
#include <cuda_runtime.h>

// SinusoidalEmbedding: out[b][s][d] = emb_table[x[b][s]][d] + PE[s][d]
// PE[s][2i] = sin(s*f_i), PE[s][2i+1] = cos(s*f_i), f_i = 10000^(-2i/1024)
//
// Flat memory-bound layout:
//   grid.x = 4096 (one CTA per position s), 256 threads (one per float4 of D).
//   No shared memory, no barriers -> full 64-warp/SM occupancy.
//   Each thread computes its 2 (sin,cos) pairs directly (warp-level trig cost
//   is negligible: ~65K warp sincosf total), then does 8 independent
//   gather+add+store (b=0..7) fully unrolled for MLP=8 per warp.

#define D_M4    256      // D_M/4
#define BQ      8
#define S_LEN   4096

__global__ __launch_bounds__(256)
void sinemb_kernel(const void* __restrict__ xraw,
                   const float* __restrict__ emb,
                   float* __restrict__ out)
{
    const int t = threadIdx.x;          // float4 index within D: d = 4t..4t+3
    const int s = blockIdx.x;           // position

    // ---- index dtype detect (int64 vs int32), uniform broadcast loads ----
    // int64 LE with values < 50257 => all high words zero; for int32 the odd
    // words are independent random indices, P(4 zeros) ~ (2e-5)^4 ~ 0.
    const unsigned int* w = (const unsigned int*)xraw;
    const bool is64 = ((w[1] | w[3] | w[5] | w[7]) == 0u);

    // ---- gather rows for this position across the batch (uniform per CTA) ----
    int rows[BQ];
    if (is64) {
        const long long* x64 = (const long long*)xraw;
        #pragma unroll
        for (int b = 0; b < BQ; b++) rows[b] = (int)x64[(long long)b * S_LEN + s];
    } else {
        const int* x32 = (const int*)xraw;
        #pragma unroll
        for (int b = 0; b < BQ; b++) rows[b] = x32[b * S_LEN + s];
    }

    // ---- positional encoding for this thread's float4 ----
    // f_i = 2^(c_exp * i), c_exp = -2*log2(10000)/1024
    const float c_exp = -0.02595256324130752f;
    const float fs = (float)s;
    float f0 = exp2f(c_exp * (float)(2 * t));
    float f1 = exp2f(c_exp * (float)(2 * t + 1));
    float4 p;
    sincosf(fs * f0, &p.x, &p.y);
    sincosf(fs * f1, &p.z, &p.w);

    // ---- 8 independent gather + add + store (coalesced float4) ----
    const float4* emb4 = (const float4*)emb;
    float4*       out4 = (float4*)out;
    #pragma unroll
    for (int b = 0; b < BQ; b++) {
        float4 e = __ldg(&emb4[(long long)rows[b] * D_M4 + t]);
        float4 o;
        o.x = e.x + p.x; o.y = e.y + p.y;
        o.z = e.z + p.z; o.w = e.w + p.w;
        out4[((long long)b * S_LEN + s) * D_M4 + t] = o;
    }
}

extern "C" void kernel_launch(void* const* d_in, const int* in_sizes, int n_in,
                              void* d_out, int out_size)
{
    const void*  x   = d_in[0];                 // [8, 4096] int64 (or int32)
    const float* emb = (const float*)d_in[1];   // [50257, 1024] fp32
    float*       out = (float*)d_out;           // [8, 4096, 1024] fp32

    sinemb_kernel<<<S_LEN, 256>>>(x, emb, out);
}